// round 11
// baseline (speedup 1.0000x reference)
#include <cuda_runtime.h>
#include <cuda_bf16.h>

#define Tn   128
#define Bn   128
#define INn  512
#define Hn   512
#define H4n  2048
#define OUTn 512
#define TBn  (Tn * Bn)

// ------------------------- device scratch (no allocs) -----------------------
__device__ float g_xw[2][TBn * H4n];
__device__ float g_h [2][TBn * Hn];
__device__ float g_c [2][Bn * Hn];
__device__ unsigned g_bar_count = 0;
__device__ unsigned g_bar_gen   = 0;

// ------------------------- f32x2 helpers ------------------------------------
__device__ __forceinline__ unsigned long long ffma2(unsigned long long a,
                                                    unsigned long long b,
                                                    unsigned long long c) {
    unsigned long long d;
    asm("fma.rn.f32x2 %0, %1, %2, %3;" : "=l"(d) : "l"(a), "l"(b), "l"(c));
    return d;
}
__device__ __forceinline__ float2 u2f2(unsigned long long v) {
    float2 r;
    asm("mov.b64 {%0, %1}, %2;" : "=f"(r.x), "=f"(r.y) : "l"(v));
    return r;
}

// ---------------------------------------------------------------------------
// Kernel 1: xw[dir] = x(, time-reversed for dir=1) @ W_ih^T + b_ih + b_hh
// M=16384, N=2048, K=512.  Tile 64x64x16, 128 threads, 8x4 outputs/thread.
// ---------------------------------------------------------------------------
__global__ void __launch_bounds__(128) xw_gemm(
    const float* __restrict__ x,
    const float* __restrict__ Wf, const float* __restrict__ bif, const float* __restrict__ bhf,
    const float* __restrict__ Wb, const float* __restrict__ bib, const float* __restrict__ bhb)
{
    const int dir = blockIdx.z;
    const float* __restrict__ W  = dir ? Wb  : Wf;
    const float* __restrict__ bi = dir ? bib : bif;
    const float* __restrict__ bh = dir ? bhb : bhf;
    float* __restrict__ outp = g_xw[dir];

    __shared__ __align__(16) float  As[16][64];
    __shared__ __align__(16) float2 Bs[16][64];

    const int tid = threadIdx.x;
    const int tx  = tid & 15;
    const int ty  = tid >> 4;
    const int m0  = blockIdx.y * 64;
    const int n0  = blockIdx.x * 64;

    const int t     = m0 >> 7;
    const int b0    = m0 & 127;
    const int xrow0 = (dir ? (Tn - 1 - t) : t) * Bn + b0;

    const int lr = tid >> 1;
    const int lk = (tid & 1) * 8;

    unsigned long long acc[4][4];
#pragma unroll
    for (int i = 0; i < 4; i++)
#pragma unroll
        for (int j = 0; j < 4; j++) acc[i][j] = 0ull;

    float4 av0, av1, bv0, bv1;
    {
        const float4* ap = (const float4*)(x + (size_t)(xrow0 + lr) * INn + lk);
        av0 = ap[0]; av1 = ap[1];
        const float4* bp = (const float4*)(W + (size_t)(n0 + lr) * INn + lk);
        bv0 = bp[0]; bv1 = bp[1];
    }

    for (int k0 = 0; k0 < INn; k0 += 16) {
        __syncthreads();
        As[lk + 0][lr] = av0.x; As[lk + 1][lr] = av0.y;
        As[lk + 2][lr] = av0.z; As[lk + 3][lr] = av0.w;
        As[lk + 4][lr] = av1.x; As[lk + 5][lr] = av1.y;
        As[lk + 6][lr] = av1.z; As[lk + 7][lr] = av1.w;
        Bs[lk + 0][lr] = make_float2(bv0.x, bv0.x);
        Bs[lk + 1][lr] = make_float2(bv0.y, bv0.y);
        Bs[lk + 2][lr] = make_float2(bv0.z, bv0.z);
        Bs[lk + 3][lr] = make_float2(bv0.w, bv0.w);
        Bs[lk + 4][lr] = make_float2(bv1.x, bv1.x);
        Bs[lk + 5][lr] = make_float2(bv1.y, bv1.y);
        Bs[lk + 6][lr] = make_float2(bv1.z, bv1.z);
        Bs[lk + 7][lr] = make_float2(bv1.w, bv1.w);
        __syncthreads();

        if (k0 + 16 < INn) {
            const float4* ap = (const float4*)(x + (size_t)(xrow0 + lr) * INn + k0 + 16 + lk);
            av0 = ap[0]; av1 = ap[1];
            const float4* bp = (const float4*)(W + (size_t)(n0 + lr) * INn + k0 + 16 + lk);
            bv0 = bp[0]; bv1 = bp[1];
        }

#pragma unroll
        for (int k = 0; k < 16; k++) {
            const ulonglong2 a01 = *(const ulonglong2*)&As[k][ty * 8];
            const ulonglong2 a23 = *(const ulonglong2*)&As[k][ty * 8 + 4];
            const ulonglong2 b01 = *(const ulonglong2*)&Bs[k][tx * 4];
            const ulonglong2 b23 = *(const ulonglong2*)&Bs[k][tx * 4 + 2];
            acc[0][0] = ffma2(a01.x, b01.x, acc[0][0]);
            acc[0][1] = ffma2(a01.x, b01.y, acc[0][1]);
            acc[0][2] = ffma2(a01.x, b23.x, acc[0][2]);
            acc[0][3] = ffma2(a01.x, b23.y, acc[0][3]);
            acc[1][0] = ffma2(a01.y, b01.x, acc[1][0]);
            acc[1][1] = ffma2(a01.y, b01.y, acc[1][1]);
            acc[1][2] = ffma2(a01.y, b23.x, acc[1][2]);
            acc[1][3] = ffma2(a01.y, b23.y, acc[1][3]);
            acc[2][0] = ffma2(a23.x, b01.x, acc[2][0]);
            acc[2][1] = ffma2(a23.x, b01.y, acc[2][1]);
            acc[2][2] = ffma2(a23.x, b23.x, acc[2][2]);
            acc[2][3] = ffma2(a23.x, b23.y, acc[2][3]);
            acc[3][0] = ffma2(a23.y, b01.x, acc[3][0]);
            acc[3][1] = ffma2(a23.y, b01.y, acc[3][1]);
            acc[3][2] = ffma2(a23.y, b23.x, acc[3][2]);
            acc[3][3] = ffma2(a23.y, b23.y, acc[3][3]);
        }
    }

    const float4 bi4 = *(const float4*)(bi + n0 + tx * 4);
    const float4 bh4 = *(const float4*)(bh + n0 + tx * 4);
    const float s0 = bi4.x + bh4.x, s1 = bi4.y + bh4.y;
    const float s2 = bi4.z + bh4.z, s3 = bi4.w + bh4.w;

#pragma unroll
    for (int i = 0; i < 4; i++) {
        const float2 c0 = u2f2(acc[i][0]);
        const float2 c1 = u2f2(acc[i][1]);
        const float2 c2 = u2f2(acc[i][2]);
        const float2 c3 = u2f2(acc[i][3]);
        const int r0 = m0 + ty * 8 + i * 2;
        *(float4*)(outp + (size_t)r0 * H4n + n0 + tx * 4) =
            make_float4(c0.x + s0, c1.x + s1, c2.x + s2, c3.x + s3);
        *(float4*)(outp + (size_t)(r0 + 1) * H4n + n0 + tx * 4) =
            make_float4(c0.y + s0, c1.y + s1, c2.y + s2, c3.y + s3);
    }
}

// ------------------------- grid-wide generation barrier ---------------------
__device__ __forceinline__ void grid_sync() {
    __syncthreads();
    if (threadIdx.x == 0) {
        __threadfence();
        const unsigned gen = atomicAdd(&g_bar_gen, 0u);
        const unsigned arrived = atomicAdd(&g_bar_count, 1u);
        if (arrived == gridDim.x - 1) {
            atomicExch(&g_bar_count, 0u);
            __threadfence();
            atomicAdd(&g_bar_gen, 1u);
        } else {
            while (atomicAdd(&g_bar_gen, 0u) == gen) { __nanosleep(64); }
        }
        __threadfence();
    }
    __syncthreads();
}

// ---------------------------------------------------------------------------
// Kernel 2: persistent bidirectional recurrence. 128 CTAs, 1/SM (164KB smem).
// CTA (dir = cta>>6, j = cta&63) owns gate cols {g*512 + j*8 + u : g<4,u<8}.
// ---------------------------------------------------------------------------
#define WS_STR 34
#define HS_STR 132
#define GS_STR 33
#define REC_WS (512 * WS_STR * 8)                  // 139264 B
#define REC_HS (16 * HS_STR * 4)                   //   8448 B
#define REC_GS (128 * GS_STR * 4)                  //  16896 B
#define REC_SMEM (REC_WS + REC_HS + REC_GS)        // 164608 B

__global__ void __launch_bounds__(256, 1) lstm_rec(
    const float* __restrict__ Whf, const float* __restrict__ Whb)
{
    extern __shared__ __align__(16) char smem[];
    float2* Ws = (float2*)smem;
    float*  Hs = (float*)(smem + REC_WS);
    float*  Gs = (float*)(smem + REC_WS + REC_HS);

    const int cta = blockIdx.x;
    const int dir = cta >> 6;
    const int j   = cta & 63;
    const float* __restrict__ Whh = dir ? Whb : Whf;
    const float* __restrict__ xw  = g_xw[dir];
    float* __restrict__ hbuf = g_h[dir];
    float* __restrict__ cbuf = g_c[dir];

    const int tid = threadIdx.x;
    const int tx  = tid & 15;
    const int ty  = tid >> 4;

    for (int idx = tid; idx < 32 * 512; idx += 256) {
        const int n = idx >> 9;
        const int k = idx & 511;
        const float w = Whh[(size_t)((n >> 3) * Hn + j * 8 + (n & 7)) * Hn + k];
        Ws[k * WS_STR + n] = make_float2(w, w);
    }
    __syncthreads();

    for (int t = 0; t < Tn; t++) {
        const int tw = dir ? (Tn - 1 - t) : t;

        unsigned long long acc[4][2];
#pragma unroll
        for (int i = 0; i < 4; i++) { acc[i][0] = 0ull; acc[i][1] = 0ull; }

        if (t > 0) {
            const float* __restrict__ hprev =
                hbuf + (size_t)(dir ? (tw + 1) : (t - 1)) * (Bn * Hn);
            float rbuf[8];
#pragma unroll
            for (int r = 0; r < 8; r++) {
                const int idx = tid + r * 256;
                rbuf[r] = hprev[(idx >> 4) * Hn + (idx & 15)];
            }
            for (int k0 = 0; k0 < Hn; k0 += 16) {
                __syncthreads();
#pragma unroll
                for (int r = 0; r < 8; r++) {
                    const int idx = tid + r * 256;
                    Hs[(idx & 15) * HS_STR + (idx >> 4)] = rbuf[r];
                }
                __syncthreads();
                if (k0 + 16 < Hn) {
#pragma unroll
                    for (int r = 0; r < 8; r++) {
                        const int idx = tid + r * 256;
                        rbuf[r] = hprev[(idx >> 4) * Hn + k0 + 16 + (idx & 15)];
                    }
                }
#pragma unroll
                for (int k = 0; k < 16; k++) {
                    const ulonglong2 a01 = *(const ulonglong2*)&Hs[k * HS_STR + ty * 8];
                    const ulonglong2 a23 = *(const ulonglong2*)&Hs[k * HS_STR + ty * 8 + 4];
                    const ulonglong2 bb  = *(const ulonglong2*)&Ws[(k0 + k) * WS_STR + tx * 2];
                    acc[0][0] = ffma2(a01.x, bb.x, acc[0][0]);
                    acc[0][1] = ffma2(a01.x, bb.y, acc[0][1]);
                    acc[1][0] = ffma2(a01.y, bb.x, acc[1][0]);
                    acc[1][1] = ffma2(a01.y, bb.y, acc[1][1]);
                    acc[2][0] = ffma2(a23.x, bb.x, acc[2][0]);
                    acc[2][1] = ffma2(a23.x, bb.y, acc[2][1]);
                    acc[3][0] = ffma2(a23.y, bb.x, acc[3][0]);
                    acc[3][1] = ffma2(a23.y, bb.y, acc[3][1]);
                }
            }
        }

#pragma unroll
        for (int i = 0; i < 4; i++) {
            const float2 c0 = u2f2(acc[i][0]);
            const float2 c1 = u2f2(acc[i][1]);
            const int r = ty * 8 + i * 2;
            Gs[r * GS_STR + tx * 2]           = c0.x;
            Gs[r * GS_STR + tx * 2 + 1]       = c1.x;
            Gs[(r + 1) * GS_STR + tx * 2]     = c0.y;
            Gs[(r + 1) * GS_STR + tx * 2 + 1] = c1.y;
        }
        __syncthreads();

        const float* __restrict__ xwt = xw + (size_t)t * (Bn * H4n);
        float* __restrict__ hout = hbuf + (size_t)tw * (Bn * Hn);
#pragma unroll
        for (int q = 0; q < 4; q++) {
            const int cell = tid + q * 256;
            const int b = cell >> 3;
            const int u = cell & 7;
            const float* __restrict__ xr = xwt + (size_t)b * H4n + j * 8 + u;
            const float pi = Gs[b * GS_STR + u]      + xr[0];
            const float pf = Gs[b * GS_STR + 8 + u]  + xr[512];
            const float pg = Gs[b * GS_STR + 16 + u] + xr[1024];
            const float po = Gs[b * GS_STR + 24 + u] + xr[1536];
            const float iv = 1.f / (1.f + __expf(-pi));
            const float fv = 1.f / (1.f + __expf(-pf));
            const float gv = tanhf(pg);
            const float ov = 1.f / (1.f + __expf(-po));
            const int ci = b * Hn + j * 8 + u;
            float c = (t == 0) ? 0.f : cbuf[ci];
            c = fv * c + iv * gv;
            cbuf[ci] = c;
            hout[ci] = ov * tanhf(c);
        }

        grid_sync();
    }
}

// ---------------------------------------------------------------------------
// Kernel 3: out = [h_fwd | h_bwd] @ W_lin^T + b_lin.  M=16384,N=512,K=1024.
// ---------------------------------------------------------------------------
__global__ void __launch_bounds__(128) out_gemm(
    const float* __restrict__ Wlin, const float* __restrict__ blin,
    float* __restrict__ out)
{
    __shared__ __align__(16) float  As[16][64];
    __shared__ __align__(16) float2 Bs[16][64];

    const int tid = threadIdx.x;
    const int tx  = tid & 15;
    const int ty  = tid >> 4;
    const int m0  = blockIdx.y * 64;
    const int n0  = blockIdx.x * 64;
    const int lr  = tid >> 1;
    const int lk  = (tid & 1) * 8;

    unsigned long long acc[4][4];
#pragma unroll
    for (int i = 0; i < 4; i++)
#pragma unroll
        for (int j = 0; j < 4; j++) acc[i][j] = 0ull;

    float4 av0, av1, bv0, bv1;
    {
        const float4* ap = (const float4*)(g_h[0] + (size_t)(m0 + lr) * Hn + lk);
        av0 = ap[0]; av1 = ap[1];
        const float4* bp = (const float4*)(Wlin + (size_t)(n0 + lr) * (2 * Hn) + lk);
        bv0 = bp[0]; bv1 = bp[1];
    }

    for (int k0 = 0; k0 < 2 * Hn; k0 += 16) {
        __syncthreads();
        As[lk + 0][lr] = av0.x; As[lk + 1][lr] = av0.y;
        As[lk + 2][lr] = av0.z; As[lk + 3][lr] = av0.w;
        As[lk + 4][lr] = av1.x; As[lk + 5][lr] = av1.y;
        As[lk + 6][lr] = av1.z; As[lk + 7][lr] = av1.w;
        Bs[lk + 0][lr] = make_float2(bv0.x, bv0.x);
        Bs[lk + 1][lr] = make_float2(bv0.y, bv0.y);
        Bs[lk + 2][lr] = make_float2(bv0.z, bv0.z);
        Bs[lk + 3][lr] = make_float2(bv0.w, bv0.w);
        Bs[lk + 4][lr] = make_float2(bv1.x, bv1.x);
        Bs[lk + 5][lr] = make_float2(bv1.y, bv1.y);
        Bs[lk + 6][lr] = make_float2(bv1.z, bv1.z);
        Bs[lk + 7][lr] = make_float2(bv1.w, bv1.w);
        __syncthreads();

        const int kn = k0 + 16;
        if (kn < 2 * Hn) {
            const float* abase = (kn < Hn) ? (g_h[0] + (size_t)(m0 + lr) * Hn + kn)
                                           : (g_h[1] + (size_t)(m0 + lr) * Hn + (kn - Hn));
            const float4* ap = (const float4*)(abase + lk);
            av0 = ap[0]; av1 = ap[1];
            const float4* bp = (const float4*)(Wlin + (size_t)(n0 + lr) * (2 * Hn) + kn + lk);
            bv0 = bp[0]; bv1 = bp[1];
        }

#pragma unroll
        for (int k = 0; k < 16; k++) {
            const ulonglong2 a01 = *(const ulonglong2*)&As[k][ty * 8];
            const ulonglong2 a23 = *(const ulonglong2*)&As[k][ty * 8 + 4];
            const ulonglong2 b01 = *(const ulonglong2*)&Bs[k][tx * 4];
            const ulonglong2 b23 = *(const ulonglong2*)&Bs[k][tx * 4 + 2];
            acc[0][0] = ffma2(a01.x, b01.x, acc[0][0]);
            acc[0][1] = ffma2(a01.x, b01.y, acc[0][1]);
            acc[0][2] = ffma2(a01.x, b23.x, acc[0][2]);
            acc[0][3] = ffma2(a01.x, b23.y, acc[0][3]);
            acc[1][0] = ffma2(a01.y, b01.x, acc[1][0]);
            acc[1][1] = ffma2(a01.y, b01.y, acc[1][1]);
            acc[1][2] = ffma2(a01.y, b23.x, acc[1][2]);
            acc[1][3] = ffma2(a01.y, b23.y, acc[1][3]);
            acc[2][0] = ffma2(a23.x, b01.x, acc[2][0]);
            acc[2][1] = ffma2(a23.x, b01.y, acc[2][1]);
            acc[2][2] = ffma2(a23.x, b23.x, acc[2][2]);
            acc[2][3] = ffma2(a23.x, b23.y, acc[2][3]);
            acc[3][0] = ffma2(a23.y, b01.x, acc[3][0]);
            acc[3][1] = ffma2(a23.y, b01.y, acc[3][1]);
            acc[3][2] = ffma2(a23.y, b23.x, acc[3][2]);
            acc[3][3] = ffma2(a23.y, b23.y, acc[3][3]);
        }
    }

    const float4 b4 = *(const float4*)(blin + n0 + tx * 4);
#pragma unroll
    for (int i = 0; i < 4; i++) {
        const float2 c0 = u2f2(acc[i][0]);
        const float2 c1 = u2f2(acc[i][1]);
        const float2 c2 = u2f2(acc[i][2]);
        const float2 c3 = u2f2(acc[i][3]);
        const int r0 = m0 + ty * 8 + i * 2;
        *(float4*)(out + (size_t)r0 * OUTn + n0 + tx * 4) =
            make_float4(c0.x + b4.x, c1.x + b4.y, c2.x + b4.z, c3.x + b4.w);
        *(float4*)(out + (size_t)(r0 + 1) * OUTn + n0 + tx * 4) =
            make_float4(c0.y + b4.x, c1.y + b4.y, c2.y + b4.z, c3.y + b4.w);
    }
}

// ---------------------------------------------------------------------------
extern "C" void kernel_launch(void* const* d_in, const int* in_sizes, int n_in,
                              void* d_out, int out_size) {
    const float* x    = (const float*)d_in[0];
    const float* Wif  = (const float*)d_in[1];
    const float* Whf  = (const float*)d_in[2];
    const float* bif  = (const float*)d_in[3];
    const float* bhf  = (const float*)d_in[4];
    const float* Wib  = (const float*)d_in[5];
    const float* Whb  = (const float*)d_in[6];
    const float* bib  = (const float*)d_in[7];
    const float* bhb  = (const float*)d_in[8];
    const float* Wlin = (const float*)d_in[9];
    const float* blin = (const float*)d_in[10];
    float* out = (float*)d_out;

    cudaFuncSetAttribute(lstm_rec, cudaFuncAttributeMaxDynamicSharedMemorySize, REC_SMEM);

    dim3 g1(H4n / 64, TBn / 64, 2);
    xw_gemm<<<g1, 128>>>(x, Wif, bif, bhf, Wib, bib, bhb);

    lstm_rec<<<128, 256, REC_SMEM>>>(Whf, Whb);

    dim3 g3(OUTn / 64, TBn / 64, 1);
    out_gemm<<<g3, 128>>>(Wlin, blin, out);
}

// round 12
// speedup vs baseline: 1.0263x; 1.0263x over previous
#include <cuda_runtime.h>
#include <cuda_bf16.h>

#define Tn   128
#define Bn   128
#define INn  512
#define Hn   512
#define H4n  2048
#define OUTn 512
#define TBn  (Tn * Bn)

// ------------------------- device scratch (no allocs) -----------------------
__device__ float g_xw[2][TBn * H4n];
__device__ float g_h [2][TBn * Hn];
__device__ float g_c [2][Bn * Hn];
__device__ unsigned g_bar_count = 0;
__device__ unsigned g_bar_gen   = 0;

// ------------------------- f32x2 helpers ------------------------------------
__device__ __forceinline__ unsigned long long ffma2(unsigned long long a,
                                                    unsigned long long b,
                                                    unsigned long long c) {
    unsigned long long d;
    asm("fma.rn.f32x2 %0, %1, %2, %3;" : "=l"(d) : "l"(a), "l"(b), "l"(c));
    return d;
}
__device__ __forceinline__ float2 u2f2(unsigned long long v) {
    float2 r;
    asm("mov.b64 {%0, %1}, %2;" : "=f"(r.x), "=f"(r.y) : "l"(v));
    return r;
}

// ---------------------------------------------------------------------------
// Kernel 1: xw[dir] = x(, time-reversed for dir=1) @ W_ih^T + b_ih + b_hh
// M=16384, N=2048, K=512.  Tile 64x64x16, 128 threads, 8x4 outputs/thread.
// ---------------------------------------------------------------------------
__global__ void __launch_bounds__(128) xw_gemm(
    const float* __restrict__ x,
    const float* __restrict__ Wf, const float* __restrict__ bif, const float* __restrict__ bhf,
    const float* __restrict__ Wb, const float* __restrict__ bib, const float* __restrict__ bhb)
{
    const int dir = blockIdx.z;
    const float* __restrict__ W  = dir ? Wb  : Wf;
    const float* __restrict__ bi = dir ? bib : bif;
    const float* __restrict__ bh = dir ? bhb : bhf;
    float* __restrict__ outp = g_xw[dir];

    __shared__ __align__(16) float  As[16][64];
    __shared__ __align__(16) float2 Bs[16][64];

    const int tid = threadIdx.x;
    const int tx  = tid & 15;
    const int ty  = tid >> 4;
    const int m0  = blockIdx.y * 64;
    const int n0  = blockIdx.x * 64;

    const int t     = m0 >> 7;
    const int b0    = m0 & 127;
    const int xrow0 = (dir ? (Tn - 1 - t) : t) * Bn + b0;

    const int lr = tid >> 1;
    const int lk = (tid & 1) * 8;

    unsigned long long acc[4][4];
#pragma unroll
    for (int i = 0; i < 4; i++)
#pragma unroll
        for (int j = 0; j < 4; j++) acc[i][j] = 0ull;

    float4 av0, av1, bv0, bv1;
    {
        const float4* ap = (const float4*)(x + (size_t)(xrow0 + lr) * INn + lk);
        av0 = ap[0]; av1 = ap[1];
        const float4* bp = (const float4*)(W + (size_t)(n0 + lr) * INn + lk);
        bv0 = bp[0]; bv1 = bp[1];
    }

    for (int k0 = 0; k0 < INn; k0 += 16) {
        __syncthreads();
        As[lk + 0][lr] = av0.x; As[lk + 1][lr] = av0.y;
        As[lk + 2][lr] = av0.z; As[lk + 3][lr] = av0.w;
        As[lk + 4][lr] = av1.x; As[lk + 5][lr] = av1.y;
        As[lk + 6][lr] = av1.z; As[lk + 7][lr] = av1.w;
        Bs[lk + 0][lr] = make_float2(bv0.x, bv0.x);
        Bs[lk + 1][lr] = make_float2(bv0.y, bv0.y);
        Bs[lk + 2][lr] = make_float2(bv0.z, bv0.z);
        Bs[lk + 3][lr] = make_float2(bv0.w, bv0.w);
        Bs[lk + 4][lr] = make_float2(bv1.x, bv1.x);
        Bs[lk + 5][lr] = make_float2(bv1.y, bv1.y);
        Bs[lk + 6][lr] = make_float2(bv1.z, bv1.z);
        Bs[lk + 7][lr] = make_float2(bv1.w, bv1.w);
        __syncthreads();

        if (k0 + 16 < INn) {
            const float4* ap = (const float4*)(x + (size_t)(xrow0 + lr) * INn + k0 + 16 + lk);
            av0 = ap[0]; av1 = ap[1];
            const float4* bp = (const float4*)(W + (size_t)(n0 + lr) * INn + k0 + 16 + lk);
            bv0 = bp[0]; bv1 = bp[1];
        }

#pragma unroll
        for (int k = 0; k < 16; k++) {
            const ulonglong2 a01 = *(const ulonglong2*)&As[k][ty * 8];
            const ulonglong2 a23 = *(const ulonglong2*)&As[k][ty * 8 + 4];
            const ulonglong2 b01 = *(const ulonglong2*)&Bs[k][tx * 4];
            const ulonglong2 b23 = *(const ulonglong2*)&Bs[k][tx * 4 + 2];
            acc[0][0] = ffma2(a01.x, b01.x, acc[0][0]);
            acc[0][1] = ffma2(a01.x, b01.y, acc[0][1]);
            acc[0][2] = ffma2(a01.x, b23.x, acc[0][2]);
            acc[0][3] = ffma2(a01.x, b23.y, acc[0][3]);
            acc[1][0] = ffma2(a01.y, b01.x, acc[1][0]);
            acc[1][1] = ffma2(a01.y, b01.y, acc[1][1]);
            acc[1][2] = ffma2(a01.y, b23.x, acc[1][2]);
            acc[1][3] = ffma2(a01.y, b23.y, acc[1][3]);
            acc[2][0] = ffma2(a23.x, b01.x, acc[2][0]);
            acc[2][1] = ffma2(a23.x, b01.y, acc[2][1]);
            acc[2][2] = ffma2(a23.x, b23.x, acc[2][2]);
            acc[2][3] = ffma2(a23.x, b23.y, acc[2][3]);
            acc[3][0] = ffma2(a23.y, b01.x, acc[3][0]);
            acc[3][1] = ffma2(a23.y, b01.y, acc[3][1]);
            acc[3][2] = ffma2(a23.y, b23.x, acc[3][2]);
            acc[3][3] = ffma2(a23.y, b23.y, acc[3][3]);
        }
    }

    const float4 bi4 = *(const float4*)(bi + n0 + tx * 4);
    const float4 bh4 = *(const float4*)(bh + n0 + tx * 4);
    const float s0 = bi4.x + bh4.x, s1 = bi4.y + bh4.y;
    const float s2 = bi4.z + bh4.z, s3 = bi4.w + bh4.w;

#pragma unroll
    for (int i = 0; i < 4; i++) {
        const float2 c0 = u2f2(acc[i][0]);
        const float2 c1 = u2f2(acc[i][1]);
        const float2 c2 = u2f2(acc[i][2]);
        const float2 c3 = u2f2(acc[i][3]);
        const int r0 = m0 + ty * 8 + i * 2;
        *(float4*)(outp + (size_t)r0 * H4n + n0 + tx * 4) =
            make_float4(c0.x + s0, c1.x + s1, c2.x + s2, c3.x + s3);
        *(float4*)(outp + (size_t)(r0 + 1) * H4n + n0 + tx * 4) =
            make_float4(c0.y + s0, c1.y + s1, c2.y + s2, c3.y + s3);
    }
}

// ------------------------- grid-wide generation barrier ---------------------
__device__ __forceinline__ void grid_sync() {
    __syncthreads();
    if (threadIdx.x == 0) {
        __threadfence();
        const unsigned gen = atomicAdd(&g_bar_gen, 0u);
        const unsigned arrived = atomicAdd(&g_bar_count, 1u);
        if (arrived == gridDim.x - 1) {
            atomicExch(&g_bar_count, 0u);
            __threadfence();
            atomicAdd(&g_bar_gen, 1u);
        } else {
            while (atomicAdd(&g_bar_gen, 0u) == gen) { __nanosleep(64); }
        }
        __threadfence();
    }
    __syncthreads();
}

// ---------------------------------------------------------------------------
// Kernel 2: persistent bidirectional recurrence. 128 CTAs, 1/SM (164KB smem).
// CTA (dir = cta>>6, j = cta&63) owns gate cols {g*512 + j*8 + u : g<4,u<8}.
// ---------------------------------------------------------------------------
#define WS_STR 34
#define HS_STR 132
#define GS_STR 33
#define REC_WS (512 * WS_STR * 8)                  // 139264 B
#define REC_HS (16 * HS_STR * 4)                   //   8448 B
#define REC_GS (128 * GS_STR * 4)                  //  16896 B
#define REC_SMEM (REC_WS + REC_HS + REC_GS)        // 164608 B

__global__ void __launch_bounds__(256, 1) lstm_rec(
    const float* __restrict__ Whf, const float* __restrict__ Whb)
{
    extern __shared__ __align__(16) char smem[];
    float2* Ws = (float2*)smem;
    float*  Hs = (float*)(smem + REC_WS);
    float*  Gs = (float*)(smem + REC_WS + REC_HS);

    const int cta = blockIdx.x;
    const int dir = cta >> 6;
    const int j   = cta & 63;
    const float* __restrict__ Whh = dir ? Whb : Whf;
    const float* __restrict__ xw  = g_xw[dir];
    float* __restrict__ hbuf = g_h[dir];
    float* __restrict__ cbuf = g_c[dir];

    const int tid = threadIdx.x;
    const int tx  = tid & 15;
    const int ty  = tid >> 4;

    for (int idx = tid; idx < 32 * 512; idx += 256) {
        const int n = idx >> 9;
        const int k = idx & 511;
        const float w = Whh[(size_t)((n >> 3) * Hn + j * 8 + (n & 7)) * Hn + k];
        Ws[k * WS_STR + n] = make_float2(w, w);
    }
    __syncthreads();

    for (int t = 0; t < Tn; t++) {
        const int tw = dir ? (Tn - 1 - t) : t;

        unsigned long long acc[4][2];
#pragma unroll
        for (int i = 0; i < 4; i++) { acc[i][0] = 0ull; acc[i][1] = 0ull; }

        if (t > 0) {
            const float* __restrict__ hprev =
                hbuf + (size_t)(dir ? (tw + 1) : (t - 1)) * (Bn * Hn);
            float rbuf[8];
#pragma unroll
            for (int r = 0; r < 8; r++) {
                const int idx = tid + r * 256;
                rbuf[r] = hprev[(idx >> 4) * Hn + (idx & 15)];
            }
            for (int k0 = 0; k0 < Hn; k0 += 16) {
                __syncthreads();
#pragma unroll
                for (int r = 0; r < 8; r++) {
                    const int idx = tid + r * 256;
                    Hs[(idx & 15) * HS_STR + (idx >> 4)] = rbuf[r];
                }
                __syncthreads();
                if (k0 + 16 < Hn) {
#pragma unroll
                    for (int r = 0; r < 8; r++) {
                        const int idx = tid + r * 256;
                        rbuf[r] = hprev[(idx >> 4) * Hn + k0 + 16 + (idx & 15)];
                    }
                }
#pragma unroll
                for (int k = 0; k < 16; k++) {
                    const ulonglong2 a01 = *(const ulonglong2*)&Hs[k * HS_STR + ty * 8];
                    const ulonglong2 a23 = *(const ulonglong2*)&Hs[k * HS_STR + ty * 8 + 4];
                    const ulonglong2 bb  = *(const ulonglong2*)&Ws[(k0 + k) * WS_STR + tx * 2];
                    acc[0][0] = ffma2(a01.x, bb.x, acc[0][0]);
                    acc[0][1] = ffma2(a01.x, bb.y, acc[0][1]);
                    acc[1][0] = ffma2(a01.y, bb.x, acc[1][0]);
                    acc[1][1] = ffma2(a01.y, bb.y, acc[1][1]);
                    acc[2][0] = ffma2(a23.x, bb.x, acc[2][0]);
                    acc[2][1] = ffma2(a23.x, bb.y, acc[2][1]);
                    acc[3][0] = ffma2(a23.y, bb.x, acc[3][0]);
                    acc[3][1] = ffma2(a23.y, bb.y, acc[3][1]);
                }
            }
        }

#pragma unroll
        for (int i = 0; i < 4; i++) {
            const float2 c0 = u2f2(acc[i][0]);
            const float2 c1 = u2f2(acc[i][1]);
            const int r = ty * 8 + i * 2;
            Gs[r * GS_STR + tx * 2]           = c0.x;
            Gs[r * GS_STR + tx * 2 + 1]       = c1.x;
            Gs[(r + 1) * GS_STR + tx * 2]     = c0.y;
            Gs[(r + 1) * GS_STR + tx * 2 + 1] = c1.y;
        }
        __syncthreads();

        const float* __restrict__ xwt = xw + (size_t)t * (Bn * H4n);
        float* __restrict__ hout = hbuf + (size_t)tw * (Bn * Hn);
#pragma unroll
        for (int q = 0; q < 4; q++) {
            const int cell = tid + q * 256;
            const int b = cell >> 3;
            const int u = cell & 7;
            const float* __restrict__ xr = xwt + (size_t)b * H4n + j * 8 + u;
            const float pi = Gs[b * GS_STR + u]      + xr[0];
            const float pf = Gs[b * GS_STR + 8 + u]  + xr[512];
            const float pg = Gs[b * GS_STR + 16 + u] + xr[1024];
            const float po = Gs[b * GS_STR + 24 + u] + xr[1536];
            const float iv = 1.f / (1.f + __expf(-pi));
            const float fv = 1.f / (1.f + __expf(-pf));
            const float gv = tanhf(pg);
            const float ov = 1.f / (1.f + __expf(-po));
            const int ci = b * Hn + j * 8 + u;
            float c = (t == 0) ? 0.f : cbuf[ci];
            c = fv * c + iv * gv;
            cbuf[ci] = c;
            hout[ci] = ov * tanhf(c);
        }

        grid_sync();
    }
}

// ---------------------------------------------------------------------------
// Kernel 3: out = [h_fwd | h_bwd] @ W_lin^T + b_lin.  M=16384,N=512,K=1024.
// ---------------------------------------------------------------------------
__global__ void __launch_bounds__(128) out_gemm(
    const float* __restrict__ Wlin, const float* __restrict__ blin,
    float* __restrict__ out)
{
    __shared__ __align__(16) float  As[16][64];
    __shared__ __align__(16) float2 Bs[16][64];

    const int tid = threadIdx.x;
    const int tx  = tid & 15;
    const int ty  = tid >> 4;
    const int m0  = blockIdx.y * 64;
    const int n0  = blockIdx.x * 64;
    const int lr  = tid >> 1;
    const int lk  = (tid & 1) * 8;

    unsigned long long acc[4][4];
#pragma unroll
    for (int i = 0; i < 4; i++)
#pragma unroll
        for (int j = 0; j < 4; j++) acc[i][j] = 0ull;

    float4 av0, av1, bv0, bv1;
    {
        const float4* ap = (const float4*)(g_h[0] + (size_t)(m0 + lr) * Hn + lk);
        av0 = ap[0]; av1 = ap[1];
        const float4* bp = (const float4*)(Wlin + (size_t)(n0 + lr) * (2 * Hn) + lk);
        bv0 = bp[0]; bv1 = bp[1];
    }

    for (int k0 = 0; k0 < 2 * Hn; k0 += 16) {
        __syncthreads();
        As[lk + 0][lr] = av0.x; As[lk + 1][lr] = av0.y;
        As[lk + 2][lr] = av0.z; As[lk + 3][lr] = av0.w;
        As[lk + 4][lr] = av1.x; As[lk + 5][lr] = av1.y;
        As[lk + 6][lr] = av1.z; As[lk + 7][lr] = av1.w;
        Bs[lk + 0][lr] = make_float2(bv0.x, bv0.x);
        Bs[lk + 1][lr] = make_float2(bv0.y, bv0.y);
        Bs[lk + 2][lr] = make_float2(bv0.z, bv0.z);
        Bs[lk + 3][lr] = make_float2(bv0.w, bv0.w);
        Bs[lk + 4][lr] = make_float2(bv1.x, bv1.x);
        Bs[lk + 5][lr] = make_float2(bv1.y, bv1.y);
        Bs[lk + 6][lr] = make_float2(bv1.z, bv1.z);
        Bs[lk + 7][lr] = make_float2(bv1.w, bv1.w);
        __syncthreads();

        const int kn = k0 + 16;
        if (kn < 2 * Hn) {
            const float* abase = (kn < Hn) ? (g_h[0] + (size_t)(m0 + lr) * Hn + kn)
                                           : (g_h[1] + (size_t)(m0 + lr) * Hn + (kn - Hn));
            const float4* ap = (const float4*)(abase + lk);
            av0 = ap[0]; av1 = ap[1];
            const float4* bp = (const float4*)(Wlin + (size_t)(n0 + lr) * (2 * Hn) + kn + lk);
            bv0 = bp[0]; bv1 = bp[1];
        }

#pragma unroll
        for (int k = 0; k < 16; k++) {
            const ulonglong2 a01 = *(const ulonglong2*)&As[k][ty * 8];
            const ulonglong2 a23 = *(const ulonglong2*)&As[k][ty * 8 + 4];
            const ulonglong2 b01 = *(const ulonglong2*)&Bs[k][tx * 4];
            const ulonglong2 b23 = *(const ulonglong2*)&Bs[k][tx * 4 + 2];
            acc[0][0] = ffma2(a01.x, b01.x, acc[0][0]);
            acc[0][1] = ffma2(a01.x, b01.y, acc[0][1]);
            acc[0][2] = ffma2(a01.x, b23.x, acc[0][2]);
            acc[0][3] = ffma2(a01.x, b23.y, acc[0][3]);
            acc[1][0] = ffma2(a01.y, b01.x, acc[1][0]);
            acc[1][1] = ffma2(a01.y, b01.y, acc[1][1]);
            acc[1][2] = ffma2(a01.y, b23.x, acc[1][2]);
            acc[1][3] = ffma2(a01.y, b23.y, acc[1][3]);
            acc[2][0] = ffma2(a23.x, b01.x, acc[2][0]);
            acc[2][1] = ffma2(a23.x, b01.y, acc[2][1]);
            acc[2][2] = ffma2(a23.x, b23.x, acc[2][2]);
            acc[2][3] = ffma2(a23.x, b23.y, acc[2][3]);
            acc[3][0] = ffma2(a23.y, b01.x, acc[3][0]);
            acc[3][1] = ffma2(a23.y, b01.y, acc[3][1]);
            acc[3][2] = ffma2(a23.y, b23.x, acc[3][2]);
            acc[3][3] = ffma2(a23.y, b23.y, acc[3][3]);
        }
    }

    const float4 b4 = *(const float4*)(blin + n0 + tx * 4);
#pragma unroll
    for (int i = 0; i < 4; i++) {
        const float2 c0 = u2f2(acc[i][0]);
        const float2 c1 = u2f2(acc[i][1]);
        const float2 c2 = u2f2(acc[i][2]);
        const float2 c3 = u2f2(acc[i][3]);
        const int r0 = m0 + ty * 8 + i * 2;
        *(float4*)(out + (size_t)r0 * OUTn + n0 + tx * 4) =
            make_float4(c0.x + b4.x, c1.x + b4.y, c2.x + b4.z, c3.x + b4.w);
        *(float4*)(out + (size_t)(r0 + 1) * OUTn + n0 + tx * 4) =
            make_float4(c0.y + b4.x, c1.y + b4.y, c2.y + b4.z, c3.y + b4.w);
    }
}

// ---------------------------------------------------------------------------
extern "C" void kernel_launch(void* const* d_in, const int* in_sizes, int n_in,
                              void* d_out, int out_size) {
    const float* x    = (const float*)d_in[0];
    const float* Wif  = (const float*)d_in[1];
    const float* Whf  = (const float*)d_in[2];
    const float* bif  = (const float*)d_in[3];
    const float* bhf  = (const float*)d_in[4];
    const float* Wib  = (const float*)d_in[5];
    const float* Whb  = (const float*)d_in[6];
    const float* bib  = (const float*)d_in[7];
    const float* bhb  = (const float*)d_in[8];
    const float* Wlin = (const float*)d_in[9];
    const float* blin = (const float*)d_in[10];
    float* out = (float*)d_out;

    cudaFuncSetAttribute(lstm_rec, cudaFuncAttributeMaxDynamicSharedMemorySize, REC_SMEM);

    dim3 g1(H4n / 64, TBn / 64, 2);
    xw_gemm<<<g1, 128>>>(x, Wif, bif, bhf, Wib, bib, bhb);

    lstm_rec<<<128, 256, REC_SMEM>>>(Whf, Whb);

    dim3 g3(OUTn / 64, TBn / 64, 1);
    out_gemm<<<g3, 128>>>(Wlin, blin, out);
}

// round 13
// speedup vs baseline: 1.0280x; 1.0016x over previous
#include <cuda_runtime.h>
#include <cuda_bf16.h>

#define Tn   128
#define Bn   128
#define INn  512
#define Hn   512
#define H4n  2048
#define OUTn 512
#define TBn  (Tn * Bn)

// ------------------------- device scratch (no allocs) -----------------------
__device__ float g_xw[2][TBn * H4n];
__device__ float g_h [2][TBn * Hn];
__device__ float g_c [2][Bn * Hn];
__device__ unsigned g_bar_count = 0;
__device__ unsigned g_bar_gen   = 0;

// ------------------------- f32x2 helpers ------------------------------------
__device__ __forceinline__ unsigned long long ffma2(unsigned long long a,
                                                    unsigned long long b,
                                                    unsigned long long c) {
    unsigned long long d;
    asm("fma.rn.f32x2 %0, %1, %2, %3;" : "=l"(d) : "l"(a), "l"(b), "l"(c));
    return d;
}
__device__ __forceinline__ float2 u2f2(unsigned long long v) {
    float2 r;
    asm("mov.b64 {%0, %1}, %2;" : "=f"(r.x), "=f"(r.y) : "l"(v));
    return r;
}

// ---------------------------------------------------------------------------
// Kernel 1: xw[dir] = x(, time-reversed for dir=1) @ W_ih^T + b_ih + b_hh
// M=16384, N=2048, K=512.  Tile 64x64x16, 128 threads, 8x4 outputs/thread.
// ---------------------------------------------------------------------------
__global__ void __launch_bounds__(128) xw_gemm(
    const float* __restrict__ x,
    const float* __restrict__ Wf, const float* __restrict__ bif, const float* __restrict__ bhf,
    const float* __restrict__ Wb, const float* __restrict__ bib, const float* __restrict__ bhb)
{
    const int dir = blockIdx.z;
    const float* __restrict__ W  = dir ? Wb  : Wf;
    const float* __restrict__ bi = dir ? bib : bif;
    const float* __restrict__ bh = dir ? bhb : bhf;
    float* __restrict__ outp = g_xw[dir];

    __shared__ __align__(16) float  As[16][64];
    __shared__ __align__(16) float2 Bs[16][64];

    const int tid = threadIdx.x;
    const int tx  = tid & 15;
    const int ty  = tid >> 4;
    const int m0  = blockIdx.y * 64;
    const int n0  = blockIdx.x * 64;

    const int t     = m0 >> 7;
    const int b0    = m0 & 127;
    const int xrow0 = (dir ? (Tn - 1 - t) : t) * Bn + b0;

    const int lr = tid >> 1;
    const int lk = (tid & 1) * 8;

    unsigned long long acc[4][4];
#pragma unroll
    for (int i = 0; i < 4; i++)
#pragma unroll
        for (int j = 0; j < 4; j++) acc[i][j] = 0ull;

    float4 av0, av1, bv0, bv1;
    {
        const float4* ap = (const float4*)(x + (size_t)(xrow0 + lr) * INn + lk);
        av0 = ap[0]; av1 = ap[1];
        const float4* bp = (const float4*)(W + (size_t)(n0 + lr) * INn + lk);
        bv0 = bp[0]; bv1 = bp[1];
    }

    for (int k0 = 0; k0 < INn; k0 += 16) {
        __syncthreads();
        As[lk + 0][lr] = av0.x; As[lk + 1][lr] = av0.y;
        As[lk + 2][lr] = av0.z; As[lk + 3][lr] = av0.w;
        As[lk + 4][lr] = av1.x; As[lk + 5][lr] = av1.y;
        As[lk + 6][lr] = av1.z; As[lk + 7][lr] = av1.w;
        Bs[lk + 0][lr] = make_float2(bv0.x, bv0.x);
        Bs[lk + 1][lr] = make_float2(bv0.y, bv0.y);
        Bs[lk + 2][lr] = make_float2(bv0.z, bv0.z);
        Bs[lk + 3][lr] = make_float2(bv0.w, bv0.w);
        Bs[lk + 4][lr] = make_float2(bv1.x, bv1.x);
        Bs[lk + 5][lr] = make_float2(bv1.y, bv1.y);
        Bs[lk + 6][lr] = make_float2(bv1.z, bv1.z);
        Bs[lk + 7][lr] = make_float2(bv1.w, bv1.w);
        __syncthreads();

        if (k0 + 16 < INn) {
            const float4* ap = (const float4*)(x + (size_t)(xrow0 + lr) * INn + k0 + 16 + lk);
            av0 = ap[0]; av1 = ap[1];
            const float4* bp = (const float4*)(W + (size_t)(n0 + lr) * INn + k0 + 16 + lk);
            bv0 = bp[0]; bv1 = bp[1];
        }

#pragma unroll
        for (int k = 0; k < 16; k++) {
            const ulonglong2 a01 = *(const ulonglong2*)&As[k][ty * 8];
            const ulonglong2 a23 = *(const ulonglong2*)&As[k][ty * 8 + 4];
            const ulonglong2 b01 = *(const ulonglong2*)&Bs[k][tx * 4];
            const ulonglong2 b23 = *(const ulonglong2*)&Bs[k][tx * 4 + 2];
            acc[0][0] = ffma2(a01.x, b01.x, acc[0][0]);
            acc[0][1] = ffma2(a01.x, b01.y, acc[0][1]);
            acc[0][2] = ffma2(a01.x, b23.x, acc[0][2]);
            acc[0][3] = ffma2(a01.x, b23.y, acc[0][3]);
            acc[1][0] = ffma2(a01.y, b01.x, acc[1][0]);
            acc[1][1] = ffma2(a01.y, b01.y, acc[1][1]);
            acc[1][2] = ffma2(a01.y, b23.x, acc[1][2]);
            acc[1][3] = ffma2(a01.y, b23.y, acc[1][3]);
            acc[2][0] = ffma2(a23.x, b01.x, acc[2][0]);
            acc[2][1] = ffma2(a23.x, b01.y, acc[2][1]);
            acc[2][2] = ffma2(a23.x, b23.x, acc[2][2]);
            acc[2][3] = ffma2(a23.x, b23.y, acc[2][3]);
            acc[3][0] = ffma2(a23.y, b01.x, acc[3][0]);
            acc[3][1] = ffma2(a23.y, b01.y, acc[3][1]);
            acc[3][2] = ffma2(a23.y, b23.x, acc[3][2]);
            acc[3][3] = ffma2(a23.y, b23.y, acc[3][3]);
        }
    }

    const float4 bi4 = *(const float4*)(bi + n0 + tx * 4);
    const float4 bh4 = *(const float4*)(bh + n0 + tx * 4);
    const float s0 = bi4.x + bh4.x, s1 = bi4.y + bh4.y;
    const float s2 = bi4.z + bh4.z, s3 = bi4.w + bh4.w;

#pragma unroll
    for (int i = 0; i < 4; i++) {
        const float2 c0 = u2f2(acc[i][0]);
        const float2 c1 = u2f2(acc[i][1]);
        const float2 c2 = u2f2(acc[i][2]);
        const float2 c3 = u2f2(acc[i][3]);
        const int r0 = m0 + ty * 8 + i * 2;
        *(float4*)(outp + (size_t)r0 * H4n + n0 + tx * 4) =
            make_float4(c0.x + s0, c1.x + s1, c2.x + s2, c3.x + s3);
        *(float4*)(outp + (size_t)(r0 + 1) * H4n + n0 + tx * 4) =
            make_float4(c0.y + s0, c1.y + s1, c2.y + s2, c3.y + s3);
    }
}

// ------------------------- grid-wide generation barrier ---------------------
__device__ __forceinline__ void grid_sync() {
    __syncthreads();
    if (threadIdx.x == 0) {
        __threadfence();
        const unsigned gen = atomicAdd(&g_bar_gen, 0u);
        const unsigned arrived = atomicAdd(&g_bar_count, 1u);
        if (arrived == gridDim.x - 1) {
            atomicExch(&g_bar_count, 0u);
            __threadfence();
            atomicAdd(&g_bar_gen, 1u);
        } else {
            while (atomicAdd(&g_bar_gen, 0u) == gen) { __nanosleep(64); }
        }
        __threadfence();
    }
    __syncthreads();
}

// ---------------------------------------------------------------------------
// Kernel 2: persistent bidirectional recurrence. 128 CTAs, 1/SM (164KB smem).
// CTA (dir = cta>>6, j = cta&63) owns gate cols {g*512 + j*8 + u : g<4,u<8}.
// ---------------------------------------------------------------------------
#define WS_STR 34
#define HS_STR 132
#define GS_STR 33
#define REC_WS (512 * WS_STR * 8)                  // 139264 B
#define REC_HS (16 * HS_STR * 4)                   //   8448 B
#define REC_GS (128 * GS_STR * 4)                  //  16896 B
#define REC_SMEM (REC_WS + REC_HS + REC_GS)        // 164608 B

__global__ void __launch_bounds__(256, 1) lstm_rec(
    const float* __restrict__ Whf, const float* __restrict__ Whb)
{
    extern __shared__ __align__(16) char smem[];
    float2* Ws = (float2*)smem;
    float*  Hs = (float*)(smem + REC_WS);
    float*  Gs = (float*)(smem + REC_WS + REC_HS);

    const int cta = blockIdx.x;
    const int dir = cta >> 6;
    const int j   = cta & 63;
    const float* __restrict__ Whh = dir ? Whb : Whf;
    const float* __restrict__ xw  = g_xw[dir];
    float* __restrict__ hbuf = g_h[dir];
    float* __restrict__ cbuf = g_c[dir];

    const int tid = threadIdx.x;
    const int tx  = tid & 15;
    const int ty  = tid >> 4;

    for (int idx = tid; idx < 32 * 512; idx += 256) {
        const int n = idx >> 9;
        const int k = idx & 511;
        const float w = Whh[(size_t)((n >> 3) * Hn + j * 8 + (n & 7)) * Hn + k];
        Ws[k * WS_STR + n] = make_float2(w, w);
    }
    __syncthreads();

    for (int t = 0; t < Tn; t++) {
        const int tw = dir ? (Tn - 1 - t) : t;

        unsigned long long acc[4][2];
#pragma unroll
        for (int i = 0; i < 4; i++) { acc[i][0] = 0ull; acc[i][1] = 0ull; }

        if (t > 0) {
            const float* __restrict__ hprev =
                hbuf + (size_t)(dir ? (tw + 1) : (t - 1)) * (Bn * Hn);
            float rbuf[8];
#pragma unroll
            for (int r = 0; r < 8; r++) {
                const int idx = tid + r * 256;
                rbuf[r] = hprev[(idx >> 4) * Hn + (idx & 15)];
            }
            for (int k0 = 0; k0 < Hn; k0 += 16) {
                __syncthreads();
#pragma unroll
                for (int r = 0; r < 8; r++) {
                    const int idx = tid + r * 256;
                    Hs[(idx & 15) * HS_STR + (idx >> 4)] = rbuf[r];
                }
                __syncthreads();
                if (k0 + 16 < Hn) {
#pragma unroll
                    for (int r = 0; r < 8; r++) {
                        const int idx = tid + r * 256;
                        rbuf[r] = hprev[(idx >> 4) * Hn + k0 + 16 + (idx & 15)];
                    }
                }
#pragma unroll
                for (int k = 0; k < 16; k++) {
                    const ulonglong2 a01 = *(const ulonglong2*)&Hs[k * HS_STR + ty * 8];
                    const ulonglong2 a23 = *(const ulonglong2*)&Hs[k * HS_STR + ty * 8 + 4];
                    const ulonglong2 bb  = *(const ulonglong2*)&Ws[(k0 + k) * WS_STR + tx * 2];
                    acc[0][0] = ffma2(a01.x, bb.x, acc[0][0]);
                    acc[0][1] = ffma2(a01.x, bb.y, acc[0][1]);
                    acc[1][0] = ffma2(a01.y, bb.x, acc[1][0]);
                    acc[1][1] = ffma2(a01.y, bb.y, acc[1][1]);
                    acc[2][0] = ffma2(a23.x, bb.x, acc[2][0]);
                    acc[2][1] = ffma2(a23.x, bb.y, acc[2][1]);
                    acc[3][0] = ffma2(a23.y, bb.x, acc[3][0]);
                    acc[3][1] = ffma2(a23.y, bb.y, acc[3][1]);
                }
            }
        }

#pragma unroll
        for (int i = 0; i < 4; i++) {
            const float2 c0 = u2f2(acc[i][0]);
            const float2 c1 = u2f2(acc[i][1]);
            const int r = ty * 8 + i * 2;
            Gs[r * GS_STR + tx * 2]           = c0.x;
            Gs[r * GS_STR + tx * 2 + 1]       = c1.x;
            Gs[(r + 1) * GS_STR + tx * 2]     = c0.y;
            Gs[(r + 1) * GS_STR + tx * 2 + 1] = c1.y;
        }
        __syncthreads();

        const float* __restrict__ xwt = xw + (size_t)t * (Bn * H4n);
        float* __restrict__ hout = hbuf + (size_t)tw * (Bn * Hn);
#pragma unroll
        for (int q = 0; q < 4; q++) {
            const int cell = tid + q * 256;
            const int b = cell >> 3;
            const int u = cell & 7;
            const float* __restrict__ xr = xwt + (size_t)b * H4n + j * 8 + u;
            const float pi = Gs[b * GS_STR + u]      + xr[0];
            const float pf = Gs[b * GS_STR + 8 + u]  + xr[512];
            const float pg = Gs[b * GS_STR + 16 + u] + xr[1024];
            const float po = Gs[b * GS_STR + 24 + u] + xr[1536];
            const float iv = 1.f / (1.f + __expf(-pi));
            const float fv = 1.f / (1.f + __expf(-pf));
            const float gv = tanhf(pg);
            const float ov = 1.f / (1.f + __expf(-po));
            const int ci = b * Hn + j * 8 + u;
            float c = (t == 0) ? 0.f : cbuf[ci];
            c = fv * c + iv * gv;
            cbuf[ci] = c;
            hout[ci] = ov * tanhf(c);
        }

        grid_sync();
    }
}

// ---------------------------------------------------------------------------
// Kernel 3: out = [h_fwd | h_bwd] @ W_lin^T + b_lin.  M=16384,N=512,K=1024.
// ---------------------------------------------------------------------------
__global__ void __launch_bounds__(128) out_gemm(
    const float* __restrict__ Wlin, const float* __restrict__ blin,
    float* __restrict__ out)
{
    __shared__ __align__(16) float  As[16][64];
    __shared__ __align__(16) float2 Bs[16][64];

    const int tid = threadIdx.x;
    const int tx  = tid & 15;
    const int ty  = tid >> 4;
    const int m0  = blockIdx.y * 64;
    const int n0  = blockIdx.x * 64;
    const int lr  = tid >> 1;
    const int lk  = (tid & 1) * 8;

    unsigned long long acc[4][4];
#pragma unroll
    for (int i = 0; i < 4; i++)
#pragma unroll
        for (int j = 0; j < 4; j++) acc[i][j] = 0ull;

    float4 av0, av1, bv0, bv1;
    {
        const float4* ap = (const float4*)(g_h[0] + (size_t)(m0 + lr) * Hn + lk);
        av0 = ap[0]; av1 = ap[1];
        const float4* bp = (const float4*)(Wlin + (size_t)(n0 + lr) * (2 * Hn) + lk);
        bv0 = bp[0]; bv1 = bp[1];
    }

    for (int k0 = 0; k0 < 2 * Hn; k0 += 16) {
        __syncthreads();
        As[lk + 0][lr] = av0.x; As[lk + 1][lr] = av0.y;
        As[lk + 2][lr] = av0.z; As[lk + 3][lr] = av0.w;
        As[lk + 4][lr] = av1.x; As[lk + 5][lr] = av1.y;
        As[lk + 6][lr] = av1.z; As[lk + 7][lr] = av1.w;
        Bs[lk + 0][lr] = make_float2(bv0.x, bv0.x);
        Bs[lk + 1][lr] = make_float2(bv0.y, bv0.y);
        Bs[lk + 2][lr] = make_float2(bv0.z, bv0.z);
        Bs[lk + 3][lr] = make_float2(bv0.w, bv0.w);
        Bs[lk + 4][lr] = make_float2(bv1.x, bv1.x);
        Bs[lk + 5][lr] = make_float2(bv1.y, bv1.y);
        Bs[lk + 6][lr] = make_float2(bv1.z, bv1.z);
        Bs[lk + 7][lr] = make_float2(bv1.w, bv1.w);
        __syncthreads();

        const int kn = k0 + 16;
        if (kn < 2 * Hn) {
            const float* abase = (kn < Hn) ? (g_h[0] + (size_t)(m0 + lr) * Hn + kn)
                                           : (g_h[1] + (size_t)(m0 + lr) * Hn + (kn - Hn));
            const float4* ap = (const float4*)(abase + lk);
            av0 = ap[0]; av1 = ap[1];
            const float4* bp = (const float4*)(Wlin + (size_t)(n0 + lr) * (2 * Hn) + kn + lk);
            bv0 = bp[0]; bv1 = bp[1];
        }

#pragma unroll
        for (int k = 0; k < 16; k++) {
            const ulonglong2 a01 = *(const ulonglong2*)&As[k][ty * 8];
            const ulonglong2 a23 = *(const ulonglong2*)&As[k][ty * 8 + 4];
            const ulonglong2 b01 = *(const ulonglong2*)&Bs[k][tx * 4];
            const ulonglong2 b23 = *(const ulonglong2*)&Bs[k][tx * 4 + 2];
            acc[0][0] = ffma2(a01.x, b01.x, acc[0][0]);
            acc[0][1] = ffma2(a01.x, b01.y, acc[0][1]);
            acc[0][2] = ffma2(a01.x, b23.x, acc[0][2]);
            acc[0][3] = ffma2(a01.x, b23.y, acc[0][3]);
            acc[1][0] = ffma2(a01.y, b01.x, acc[1][0]);
            acc[1][1] = ffma2(a01.y, b01.y, acc[1][1]);
            acc[1][2] = ffma2(a01.y, b23.x, acc[1][2]);
            acc[1][3] = ffma2(a01.y, b23.y, acc[1][3]);
            acc[2][0] = ffma2(a23.x, b01.x, acc[2][0]);
            acc[2][1] = ffma2(a23.x, b01.y, acc[2][1]);
            acc[2][2] = ffma2(a23.x, b23.x, acc[2][2]);
            acc[2][3] = ffma2(a23.x, b23.y, acc[2][3]);
            acc[3][0] = ffma2(a23.y, b01.x, acc[3][0]);
            acc[3][1] = ffma2(a23.y, b01.y, acc[3][1]);
            acc[3][2] = ffma2(a23.y, b23.x, acc[3][2]);
            acc[3][3] = ffma2(a23.y, b23.y, acc[3][3]);
        }
    }

    const float4 b4 = *(const float4*)(blin + n0 + tx * 4);
#pragma unroll
    for (int i = 0; i < 4; i++) {
        const float2 c0 = u2f2(acc[i][0]);
        const float2 c1 = u2f2(acc[i][1]);
        const float2 c2 = u2f2(acc[i][2]);
        const float2 c3 = u2f2(acc[i][3]);
        const int r0 = m0 + ty * 8 + i * 2;
        *(float4*)(out + (size_t)r0 * OUTn + n0 + tx * 4) =
            make_float4(c0.x + b4.x, c1.x + b4.y, c2.x + b4.z, c3.x + b4.w);
        *(float4*)(out + (size_t)(r0 + 1) * OUTn + n0 + tx * 4) =
            make_float4(c0.y + b4.x, c1.y + b4.y, c2.y + b4.z, c3.y + b4.w);
    }
}

// ---------------------------------------------------------------------------
extern "C" void kernel_launch(void* const* d_in, const int* in_sizes, int n_in,
                              void* d_out, int out_size) {
    const float* x    = (const float*)d_in[0];
    const float* Wif  = (const float*)d_in[1];
    const float* Whf  = (const float*)d_in[2];
    const float* bif  = (const float*)d_in[3];
    const float* bhf  = (const float*)d_in[4];
    const float* Wib  = (const float*)d_in[5];
    const float* Whb  = (const float*)d_in[6];
    const float* bib  = (const float*)d_in[7];
    const float* bhb  = (const float*)d_in[8];
    const float* Wlin = (const float*)d_in[9];
    const float* blin = (const float*)d_in[10];
    float* out = (float*)d_out;

    cudaFuncSetAttribute(lstm_rec, cudaFuncAttributeMaxDynamicSharedMemorySize, REC_SMEM);

    dim3 g1(H4n / 64, TBn / 64, 2);
    xw_gemm<<<g1, 128>>>(x, Wif, bif, bhf, Wib, bib, bhb);

    lstm_rec<<<128, 256, REC_SMEM>>>(Whf, Whb);

    dim3 g3(OUTn / 64, TBn / 64, 1);
    out_gemm<<<g3, 128>>>(Wlin, blin, out);
}